// round 12
// baseline (speedup 1.0000x reference)
#include <cuda_runtime.h>
#include <cuda_bf16.h>
#include <mma.h>
#include <math.h>
#include <stdint.h>

using namespace nvcuda;

#define N_NODES  50000
#define N_EDGES  800000
#define N_GRAPHS 50
#define FEAT     256
#define M_PAD    50048      // 391 * 128

// ---------------- scratch (static device globals: no allocations) ----------
__device__ float g_bufA[(size_t)M_PAD * FEAT];     // GEMM output h (padded rows)
__device__ float g_bufB[(size_t)N_NODES * FEAT];   // aggregated/relu output
__device__ float g_asrc[N_NODES * 4];
__device__ float g_adst[N_NODES * 4];
__device__ int   g_rowptr[N_NODES + 1];
__device__ int   g_cursor[N_NODES];
__device__ int   g_esrc[N_EDGES];
__device__ float g_pool[N_GRAPHS * FEAT];
__device__ float g_cnt[N_GRAPHS];
// bf16x3 split operands for tensor-core GEMM
__device__ __nv_bfloat16 g_Ah[(size_t)M_PAD * FEAT];
__device__ __nv_bfloat16 g_Al[(size_t)M_PAD * FEAT];
__device__ __nv_bfloat16 g_Wh[FEAT * FEAT];        // W^T ([n][k]), hi split
__device__ __nv_bfloat16 g_Wl[FEAT * FEAT];        // W^T ([n][k]), lo split

// ================= WMMA bf16x3 GEMM: C[M_PAD,256] = A @ W ==================
// A splits row-major [M_PAD,256] in g_Ah/g_Al; W^T splits [n][k] in g_Wh/g_Wl
// (so W^T row-major == W col-major for the B fragment). Output fp32 g_bufA.
// Block tile 128x128, 8 warps of 32(rows) x 64(cols) each.
#define SMEM_GEMM (2 * 128 * FEAT * 2)   // hi + lo B bands: 131072 bytes

__global__ __launch_bounds__(256, 1) void k_gemm_wmma() {
    extern __shared__ __nv_bfloat16 sB[];          // [0:32768) hi, [32768:65536) lo
    __nv_bfloat16* sBh = sB;
    __nv_bfloat16* sBl = sB + 128 * FEAT;

    int tid = threadIdx.x;
    int w = tid >> 5;
    int warp_m = w >> 1;                           // 0..3
    int warp_n = w & 1;                            // 0..1
    int bm = blockIdx.x * 128;
    int bn = blockIdx.y * 128;

    // stage B band (n = bn..bn+127, all K) into smem: contiguous copy
    {
        const uint4* gh = (const uint4*)(g_Wh + (size_t)bn * FEAT);
        const uint4* gl = (const uint4*)(g_Wl + (size_t)bn * FEAT);
        uint4* shh = (uint4*)sBh;
        uint4* sll = (uint4*)sBl;
        for (int i = tid; i < 128 * FEAT / 8; i += 256) {
            shh[i] = gh[i];
            sll[i] = gl[i];
        }
    }
    __syncthreads();

    wmma::fragment<wmma::accumulator, 16, 16, 16, float> acc[2][4];
#pragma unroll
    for (int i = 0; i < 2; i++)
#pragma unroll
        for (int j = 0; j < 4; j++) wmma::fill_fragment(acc[i][j], 0.f);

    const size_t arow0 = (size_t)(bm + warp_m * 32) * FEAT;
    const int bcol0 = warp_n * 64;

    for (int kk = 0; kk < FEAT; kk += 16) {
        wmma::fragment<wmma::matrix_a, 16, 16, 16, __nv_bfloat16, wmma::row_major> ah[2], al[2];
        wmma::fragment<wmma::matrix_b, 16, 16, 16, __nv_bfloat16, wmma::col_major> bh[4], bl[4];
#pragma unroll
        for (int i = 0; i < 2; i++) {
            wmma::load_matrix_sync(ah[i], g_Ah + arow0 + (size_t)i * 16 * FEAT + kk, FEAT);
            wmma::load_matrix_sync(al[i], g_Al + arow0 + (size_t)i * 16 * FEAT + kk, FEAT);
        }
#pragma unroll
        for (int j = 0; j < 4; j++) {
            wmma::load_matrix_sync(bh[j], sBh + (size_t)(bcol0 + j * 16) * FEAT + kk, FEAT);
            wmma::load_matrix_sync(bl[j], sBl + (size_t)(bcol0 + j * 16) * FEAT + kk, FEAT);
        }
#pragma unroll
        for (int i = 0; i < 2; i++)
#pragma unroll
            for (int j = 0; j < 4; j++) {
                wmma::mma_sync(acc[i][j], ah[i], bh[j], acc[i][j]);
                wmma::mma_sync(acc[i][j], ah[i], bl[j], acc[i][j]);
                wmma::mma_sync(acc[i][j], al[i], bh[j], acc[i][j]);
            }
    }

#pragma unroll
    for (int i = 0; i < 2; i++)
#pragma unroll
        for (int j = 0; j < 4; j++) {
            float* cp = g_bufA + (size_t)(bm + warp_m * 32 + i * 16) * FEAT +
                        bn + bcol0 + j * 16;
            wmma::store_matrix_sync(cp, acc[i][j], FEAT, wmma::mem_row_major);
        }
}

// ---------------- bf16 hi/lo split of A ([M_PAD,256], zero-padded) --------
__global__ void k_split_A(const float* __restrict__ ext, int internal) {
    int i = (blockIdx.x * blockDim.x + threadIdx.x) << 2;
    if (i >= M_PAD * FEAT) return;
    float4 v = make_float4(0.f, 0.f, 0.f, 0.f);
    if ((i >> 8) < N_NODES) {
        const float* s = internal ? g_bufB : ext;
        v = *(const float4*)(s + i);
    }
    __nv_bfloat162 h01 = __floats2bfloat162_rn(v.x, v.y);
    __nv_bfloat162 h23 = __floats2bfloat162_rn(v.z, v.w);
    float2 f01 = __bfloat1622float2(h01);
    float2 f23 = __bfloat1622float2(h23);
    __nv_bfloat162 l01 = __floats2bfloat162_rn(v.x - f01.x, v.y - f01.y);
    __nv_bfloat162 l23 = __floats2bfloat162_rn(v.z - f23.x, v.w - f23.y);
    *(__nv_bfloat162*)(g_Ah + i) = h01;
    *(__nv_bfloat162*)(g_Ah + i + 2) = h23;
    *(__nv_bfloat162*)(g_Al + i) = l01;
    *(__nv_bfloat162*)(g_Al + i + 2) = l23;
}

// ---------------- bf16 hi/lo split + transpose of W ([k][n] -> [n][k]) ----
__global__ void k_split_W(const float* __restrict__ W) {
    int k = blockIdx.x, n = threadIdx.x;
    float v = W[k * FEAT + n];
    __nv_bfloat16 h = __float2bfloat16(v);
    __nv_bfloat16 l = __float2bfloat16(v - __bfloat162float(h));
    g_Wh[n * FEAT + k] = h;
    g_Wl[n * FEAT + k] = l;
}

// ---------------- zero the per-call accumulators ----------------
__global__ void k_zero() {
    int i = blockIdx.x * blockDim.x + threadIdx.x;
    if (i <= N_NODES) g_rowptr[i] = 0;
    if (i < N_GRAPHS * FEAT) g_pool[i] = 0.f;
    if (i < N_GRAPHS) g_cnt[i] = 0.f;
}

__global__ void k_deg(const int* __restrict__ dst) {
    int e = blockIdx.x * blockDim.x + threadIdx.x;
    if (e < N_EDGES) atomicAdd(&g_rowptr[dst[e] + 1], 1);
}

__global__ void k_scan() {
    const int n = N_NODES + 1;
    const int T = 1024;
    __shared__ int sums[T];
    int t = threadIdx.x;
    const int CH = (n + T - 1) / T;
    int beg = t * CH;
    int end = min(beg + CH, n);
    int s = 0;
    for (int i = beg; i < end; i++) { s += g_rowptr[i]; g_rowptr[i] = s; }
    sums[t] = s;
    __syncthreads();
    for (int off = 1; off < T; off <<= 1) {
        int v = sums[t];
        int u = (t >= off) ? sums[t - off] : 0;
        __syncthreads();
        sums[t] = v + u;
        __syncthreads();
    }
    int add = (t > 0) ? sums[t - 1] : 0;
    if (add)
        for (int i = beg; i < end; i++) g_rowptr[i] += add;
}

__global__ void k_cursor() {
    int i = blockIdx.x * blockDim.x + threadIdx.x;
    if (i < N_NODES) g_cursor[i] = g_rowptr[i];
}

__global__ void k_scatter(const int* __restrict__ src, const int* __restrict__ dst) {
    int e = blockIdx.x * blockDim.x + threadIdx.x;
    if (e < N_EDGES) {
        int pos = atomicAdd(&g_cursor[dst[e]], 1);
        g_esrc[pos] = src[e];
    }
}

// ---------------- per-node attention logits: warp per node ----------------
template <int H>
__global__ void k_att(const float* __restrict__ att_src, const float* __restrict__ att_dst) {
    int node = (blockIdx.x * blockDim.x + threadIdx.x) >> 5;
    if (node >= N_NODES) return;
    int lane = threadIdx.x & 31;
    const float4* hp = (const float4*)(g_bufA + (size_t)node * FEAT + lane * 8);
    float4 h0 = hp[0], h1 = hp[1];
    const float4* sp = (const float4*)(att_src + lane * 8);
    float4 s0 = sp[0], s1 = sp[1];
    const float4* dp = (const float4*)(att_dst + lane * 8);
    float4 d0 = dp[0], d1 = dp[1];
    float ps = h0.x * s0.x + h0.y * s0.y + h0.z * s0.z + h0.w * s0.w +
               h1.x * s1.x + h1.y * s1.y + h1.z * s1.z + h1.w * s1.w;
    float pd = h0.x * d0.x + h0.y * d0.y + h0.z * d0.z + h0.w * d0.w +
               h1.x * d1.x + h1.y * d1.y + h1.z * d1.z + h1.w * d1.w;
    constexpr int G = (FEAT / H) / 8;
#pragma unroll
    for (int off = G >> 1; off > 0; off >>= 1) {
        ps += __shfl_down_sync(0xffffffffu, ps, off, G);
        pd += __shfl_down_sync(0xffffffffu, pd, off, G);
    }
    if ((lane & (G - 1)) == 0) {
        int head = lane / G;
        g_asrc[node * H + head] = ps;
        g_adst[node * H + head] = pd;
    }
}

// ---------------- CSR aggregation with online softmax: warp per dst node --
template <int H>
__global__ void k_agg(const float* __restrict__ bias) {
    int node = (blockIdx.x * blockDim.x + threadIdx.x) >> 5;
    if (node >= N_NODES) return;
    int lane = threadIdx.x & 31;
    constexpr int G = (FEAT / H) / 8;
    int head = lane / G;
    float ad = g_adst[node * H + head];
    float m = -INFINITY, s = 0.f;
    float acc[8] = {0.f, 0.f, 0.f, 0.f, 0.f, 0.f, 0.f, 0.f};
    int beg = g_rowptr[node], end = g_rowptr[node + 1];
    for (int e = beg; e < end; e++) {
        int src = g_esrc[e];
        const float4* hp = (const float4*)(g_bufA + (size_t)src * FEAT + lane * 8);
        float4 v0 = hp[0], v1 = hp[1];
        float av = g_asrc[src * H + head] + ad;
        float ee = (av > 0.f) ? av : 0.2f * av;
        float nm = fmaxf(m, ee);
        float scale = __expf(m - nm);
        float w = __expf(ee - nm);
        m = nm;
        s = s * scale + w;
        acc[0] = acc[0] * scale + w * v0.x;
        acc[1] = acc[1] * scale + w * v0.y;
        acc[2] = acc[2] * scale + w * v0.z;
        acc[3] = acc[3] * scale + w * v0.w;
        acc[4] = acc[4] * scale + w * v1.x;
        acc[5] = acc[5] * scale + w * v1.y;
        acc[6] = acc[6] * scale + w * v1.z;
        acc[7] = acc[7] * scale + w * v1.w;
    }
    float inv = (s > 0.f) ? 1.f / s : 0.f;
    const float4* bp = (const float4*)(bias + lane * 8);
    float4 b0 = bp[0], b1 = bp[1];
    float4 o0 = make_float4(fmaxf(acc[0] * inv + b0.x, 0.f), fmaxf(acc[1] * inv + b0.y, 0.f),
                            fmaxf(acc[2] * inv + b0.z, 0.f), fmaxf(acc[3] * inv + b0.w, 0.f));
    float4 o1 = make_float4(fmaxf(acc[4] * inv + b1.x, 0.f), fmaxf(acc[5] * inv + b1.y, 0.f),
                            fmaxf(acc[6] * inv + b1.z, 0.f), fmaxf(acc[7] * inv + b1.w, 0.f));
    float4* op = (float4*)(g_bufB + (size_t)node * FEAT + lane * 8);
    op[0] = o0;
    op[1] = o1;
}

// ---------------- global mean pool (batch is sorted): run-length flush ----
__global__ void k_pool(const int* __restrict__ batch) {
    constexpr int ROWS = 128;
    __shared__ int sb[ROWS];
    int n0 = blockIdx.x * ROWS;
    int tid = threadIdx.x;
    for (int i = tid; i < ROWS; i += 256) {
        int n = n0 + i;
        sb[i] = (n < N_NODES) ? batch[n] : -1;
    }
    __syncthreads();
    float acc = 0.f;
    int cur = sb[0];
    for (int i = 0; i < ROWS; i++) {
        int g = sb[i];
        if (g < 0) break;
        if (g != cur) {
            atomicAdd(&g_pool[cur * FEAT + tid], acc);
            acc = 0.f;
            cur = g;
        }
        acc += g_bufB[(size_t)(n0 + i) * FEAT + tid];
    }
    if (cur >= 0) atomicAdd(&g_pool[cur * FEAT + tid], acc);
}

__global__ void k_cnt(const int* __restrict__ batch) {
    int n = blockIdx.x * blockDim.x + threadIdx.x;
    if (n < N_NODES) atomicAdd(&g_cnt[batch[n]], 1.f);
}

__global__ void k_fc(const float* __restrict__ Wfc, const float* __restrict__ bfc,
                     float* __restrict__ out) {
    int g = blockIdx.x;
    int tid = threadIdx.x;
    __shared__ float p[FEAT];
    float inv = 1.f / fmaxf(g_cnt[g], 1.f);
    p[tid] = g_pool[g * FEAT + tid] * inv;
    __syncthreads();
    float s = bfc[tid];
#pragma unroll 8
    for (int k = 0; k < FEAT; k++) s = fmaf(p[k], Wfc[k * FEAT + tid], s);
    out[g * FEAT + tid] = fmaxf(s, 0.f);
}

// ---------------- launcher -------------------------------------------------
extern "C" void kernel_launch(void* const* d_in, const int* in_sizes, int n_in,
                              void* d_out, int out_size) {
    const float* x        = (const float*)d_in[0];
    const int*   edges    = (const int*)d_in[1];
    const int*   batch    = (const int*)d_in[2];
    const float* W1       = (const float*)d_in[3];
    const float* att_src1 = (const float*)d_in[4];
    const float* att_dst1 = (const float*)d_in[5];
    const float* b1       = (const float*)d_in[6];
    const float* W2       = (const float*)d_in[7];
    const float* att_src2 = (const float*)d_in[8];
    const float* att_dst2 = (const float*)d_in[9];
    const float* b2       = (const float*)d_in[10];
    const float* Wfc      = (const float*)d_in[11];
    const float* bfc      = (const float*)d_in[12];
    float* out = (float*)d_out;

    const int* srcp = edges;
    const int* dstp = edges + N_EDGES;

    static int smem_set = 0;
    if (!smem_set) {
        cudaFuncSetAttribute(k_gemm_wmma, cudaFuncAttributeMaxDynamicSharedMemorySize,
                             SMEM_GEMM);
        smem_set = 1;
    }

    // zero accumulators + build CSR by destination
    k_zero<<<(N_NODES + 256) / 256, 256>>>();
    k_deg<<<(N_EDGES + 255) / 256, 256>>>(dstp);
    k_scan<<<1, 1024>>>();
    k_cursor<<<(N_NODES + 255) / 256, 256>>>();
    k_scatter<<<(N_EDGES + 255) / 256, 256>>>(srcp, dstp);

    dim3 ggrid(M_PAD / 128, FEAT / 128);   // (391, 2)
    int splitA_blocks = (M_PAD * FEAT / 4 + 255) / 256;
    int att_blocks = (N_NODES * 32 + 255) / 256;
    int agg_blocks = (N_NODES + 7) / 8;

    // layer 1 (H=4, C=64)
    k_split_W<<<FEAT, FEAT>>>(W1);
    k_split_A<<<splitA_blocks, 256>>>(x, 0);
    k_gemm_wmma<<<ggrid, 256, SMEM_GEMM>>>();
    k_att<4><<<att_blocks, 256>>>(att_src1, att_dst1);
    k_agg<4><<<agg_blocks, 256>>>(b1);

    // layer 2 (H=1, C=256)
    k_split_W<<<FEAT, FEAT>>>(W2);
    k_split_A<<<splitA_blocks, 256>>>(nullptr, 1);
    k_gemm_wmma<<<ggrid, 256, SMEM_GEMM>>>();
    k_att<1><<<att_blocks, 256>>>(att_src2, att_dst2);
    k_agg<1><<<agg_blocks, 256>>>(b2);

    // pool + FC head
    k_pool<<<(N_NODES + 127) / 128, 256>>>(batch);
    k_cnt<<<(N_NODES + 255) / 256, 256>>>(batch);
    k_fc<<<N_GRAPHS, 256>>>(Wfc, bfc, out);
}

// round 13
// speedup vs baseline: 1.0027x; 1.0027x over previous
#include <cuda_runtime.h>
#include <cuda_bf16.h>
#include <mma.h>
#include <math.h>
#include <stdint.h>

using namespace nvcuda;

#define N_NODES  50000
#define N_EDGES  800000
#define N_GRAPHS 50
#define FEAT     256
#define M_PAD    50048      // 391 * 128

// ---------------- scratch (static device globals: no allocations) ----------
__device__ float g_bufA[(size_t)M_PAD * FEAT];     // GEMM output h (padded rows)
__device__ float g_bufB[(size_t)N_NODES * FEAT];   // aggregated/relu output
__device__ float g_asrc[N_NODES * 4];
__device__ float g_adst[N_NODES * 4];
__device__ int   g_rowptr[N_NODES + 1];
__device__ int   g_cursor[N_NODES];
__device__ int   g_esrc[N_EDGES];
__device__ float g_pool[N_GRAPHS * FEAT];
__device__ float g_cnt[N_GRAPHS];
// bf16x3 split operands for tensor-core GEMM
__device__ __nv_bfloat16 g_Ah[(size_t)M_PAD * FEAT];
__device__ __nv_bfloat16 g_Al[(size_t)M_PAD * FEAT];
__device__ __nv_bfloat16 g_Wh[FEAT * FEAT];        // W^T ([n][k]), hi split
__device__ __nv_bfloat16 g_Wl[FEAT * FEAT];        // W^T ([n][k]), lo split

// ================= WMMA bf16x3 GEMM: C[M_PAD,256] = A @ W ==================
// A splits row-major [M_PAD,256] in g_Ah/g_Al; W^T splits [n][k] in g_Wh/g_Wl
// (so W^T row-major == W col-major for the B fragment). Output fp32 g_bufA.
// Block tile 128x128, 8 warps of 32(rows) x 64(cols) each.
#define SMEM_GEMM (2 * 128 * FEAT * 2)   // hi + lo B bands: 131072 bytes

__global__ __launch_bounds__(256, 1) void k_gemm_wmma() {
    extern __shared__ __nv_bfloat16 sB[];          // [0:32768) hi, [32768:65536) lo
    __nv_bfloat16* sBh = sB;
    __nv_bfloat16* sBl = sB + 128 * FEAT;

    int tid = threadIdx.x;
    int w = tid >> 5;
    int warp_m = w >> 1;                           // 0..3
    int warp_n = w & 1;                            // 0..1
    int bm = blockIdx.x * 128;
    int bn = blockIdx.y * 128;

    // stage B band (n = bn..bn+127, all K) into smem: contiguous copy
    {
        const uint4* gh = (const uint4*)(g_Wh + (size_t)bn * FEAT);
        const uint4* gl = (const uint4*)(g_Wl + (size_t)bn * FEAT);
        uint4* shh = (uint4*)sBh;
        uint4* sll = (uint4*)sBl;
        for (int i = tid; i < 128 * FEAT / 8; i += 256) {
            shh[i] = gh[i];
            sll[i] = gl[i];
        }
    }
    __syncthreads();

    wmma::fragment<wmma::accumulator, 16, 16, 16, float> acc[2][4];
#pragma unroll
    for (int i = 0; i < 2; i++)
#pragma unroll
        for (int j = 0; j < 4; j++) wmma::fill_fragment(acc[i][j], 0.f);

    const size_t arow0 = (size_t)(bm + warp_m * 32) * FEAT;
    const int bcol0 = warp_n * 64;

    for (int kk = 0; kk < FEAT; kk += 16) {
        wmma::fragment<wmma::matrix_a, 16, 16, 16, __nv_bfloat16, wmma::row_major> ah[2], al[2];
        wmma::fragment<wmma::matrix_b, 16, 16, 16, __nv_bfloat16, wmma::col_major> bh[4], bl[4];
#pragma unroll
        for (int i = 0; i < 2; i++) {
            wmma::load_matrix_sync(ah[i], g_Ah + arow0 + (size_t)i * 16 * FEAT + kk, FEAT);
            wmma::load_matrix_sync(al[i], g_Al + arow0 + (size_t)i * 16 * FEAT + kk, FEAT);
        }
#pragma unroll
        for (int j = 0; j < 4; j++) {
            wmma::load_matrix_sync(bh[j], sBh + (size_t)(bcol0 + j * 16) * FEAT + kk, FEAT);
            wmma::load_matrix_sync(bl[j], sBl + (size_t)(bcol0 + j * 16) * FEAT + kk, FEAT);
        }
#pragma unroll
        for (int i = 0; i < 2; i++)
#pragma unroll
            for (int j = 0; j < 4; j++) {
                wmma::mma_sync(acc[i][j], ah[i], bh[j], acc[i][j]);
                wmma::mma_sync(acc[i][j], ah[i], bl[j], acc[i][j]);
                wmma::mma_sync(acc[i][j], al[i], bh[j], acc[i][j]);
            }
    }

#pragma unroll
    for (int i = 0; i < 2; i++)
#pragma unroll
        for (int j = 0; j < 4; j++) {
            float* cp = g_bufA + (size_t)(bm + warp_m * 32 + i * 16) * FEAT +
                        bn + bcol0 + j * 16;
            wmma::store_matrix_sync(cp, acc[i][j], FEAT, wmma::mem_row_major);
        }
}

// ---------------- bf16 hi/lo split of A ([M_PAD,256], zero-padded) --------
__global__ void k_split_A(const float* __restrict__ ext, int internal) {
    int i = (blockIdx.x * blockDim.x + threadIdx.x) << 2;
    if (i >= M_PAD * FEAT) return;
    float4 v = make_float4(0.f, 0.f, 0.f, 0.f);
    if ((i >> 8) < N_NODES) {
        const float* s = internal ? g_bufB : ext;
        v = *(const float4*)(s + i);
    }
    __nv_bfloat162 h01 = __floats2bfloat162_rn(v.x, v.y);
    __nv_bfloat162 h23 = __floats2bfloat162_rn(v.z, v.w);
    float2 f01 = __bfloat1622float2(h01);
    float2 f23 = __bfloat1622float2(h23);
    __nv_bfloat162 l01 = __floats2bfloat162_rn(v.x - f01.x, v.y - f01.y);
    __nv_bfloat162 l23 = __floats2bfloat162_rn(v.z - f23.x, v.w - f23.y);
    *(__nv_bfloat162*)(g_Ah + i) = h01;
    *(__nv_bfloat162*)(g_Ah + i + 2) = h23;
    *(__nv_bfloat162*)(g_Al + i) = l01;
    *(__nv_bfloat162*)(g_Al + i + 2) = l23;
}

// ---------------- bf16 hi/lo split + transpose of W ([k][n] -> [n][k]) ----
__global__ void k_split_W(const float* __restrict__ W) {
    int k = blockIdx.x, n = threadIdx.x;
    float v = W[k * FEAT + n];
    __nv_bfloat16 h = __float2bfloat16(v);
    __nv_bfloat16 l = __float2bfloat16(v - __bfloat162float(h));
    g_Wh[n * FEAT + k] = h;
    g_Wl[n * FEAT + k] = l;
}

// ---------------- zero the per-call accumulators ----------------
__global__ void k_zero() {
    int i = blockIdx.x * blockDim.x + threadIdx.x;
    if (i <= N_NODES) g_rowptr[i] = 0;
    if (i < N_GRAPHS * FEAT) g_pool[i] = 0.f;
    if (i < N_GRAPHS) g_cnt[i] = 0.f;
}

__global__ void k_deg(const int* __restrict__ dst) {
    int e = blockIdx.x * blockDim.x + threadIdx.x;
    if (e < N_EDGES) atomicAdd(&g_rowptr[dst[e] + 1], 1);
}

__global__ void k_scan() {
    const int n = N_NODES + 1;
    const int T = 1024;
    __shared__ int sums[T];
    int t = threadIdx.x;
    const int CH = (n + T - 1) / T;
    int beg = t * CH;
    int end = min(beg + CH, n);
    int s = 0;
    for (int i = beg; i < end; i++) { s += g_rowptr[i]; g_rowptr[i] = s; }
    sums[t] = s;
    __syncthreads();
    for (int off = 1; off < T; off <<= 1) {
        int v = sums[t];
        int u = (t >= off) ? sums[t - off] : 0;
        __syncthreads();
        sums[t] = v + u;
        __syncthreads();
    }
    int add = (t > 0) ? sums[t - 1] : 0;
    if (add)
        for (int i = beg; i < end; i++) g_rowptr[i] += add;
}

__global__ void k_cursor() {
    int i = blockIdx.x * blockDim.x + threadIdx.x;
    if (i < N_NODES) g_cursor[i] = g_rowptr[i];
}

__global__ void k_scatter(const int* __restrict__ src, const int* __restrict__ dst) {
    int e = blockIdx.x * blockDim.x + threadIdx.x;
    if (e < N_EDGES) {
        int pos = atomicAdd(&g_cursor[dst[e]], 1);
        g_esrc[pos] = src[e];
    }
}

// ---------------- per-node attention logits: warp per node ----------------
template <int H>
__global__ void k_att(const float* __restrict__ att_src, const float* __restrict__ att_dst) {
    int node = (blockIdx.x * blockDim.x + threadIdx.x) >> 5;
    if (node >= N_NODES) return;
    int lane = threadIdx.x & 31;
    const float4* hp = (const float4*)(g_bufA + (size_t)node * FEAT + lane * 8);
    float4 h0 = hp[0], h1 = hp[1];
    const float4* sp = (const float4*)(att_src + lane * 8);
    float4 s0 = sp[0], s1 = sp[1];
    const float4* dp = (const float4*)(att_dst + lane * 8);
    float4 d0 = dp[0], d1 = dp[1];
    float ps = h0.x * s0.x + h0.y * s0.y + h0.z * s0.z + h0.w * s0.w +
               h1.x * s1.x + h1.y * s1.y + h1.z * s1.z + h1.w * s1.w;
    float pd = h0.x * d0.x + h0.y * d0.y + h0.z * d0.z + h0.w * d0.w +
               h1.x * d1.x + h1.y * d1.y + h1.z * d1.z + h1.w * d1.w;
    constexpr int G = (FEAT / H) / 8;
#pragma unroll
    for (int off = G >> 1; off > 0; off >>= 1) {
        ps += __shfl_down_sync(0xffffffffu, ps, off, G);
        pd += __shfl_down_sync(0xffffffffu, pd, off, G);
    }
    if ((lane & (G - 1)) == 0) {
        int head = lane / G;
        g_asrc[node * H + head] = ps;
        g_adst[node * H + head] = pd;
    }
}

// ---------------- CSR aggregation with online softmax: warp per dst node --
template <int H>
__global__ void k_agg(const float* __restrict__ bias) {
    int node = (blockIdx.x * blockDim.x + threadIdx.x) >> 5;
    if (node >= N_NODES) return;
    int lane = threadIdx.x & 31;
    constexpr int G = (FEAT / H) / 8;
    int head = lane / G;
    float ad = g_adst[node * H + head];
    float m = -INFINITY, s = 0.f;
    float acc[8] = {0.f, 0.f, 0.f, 0.f, 0.f, 0.f, 0.f, 0.f};
    int beg = g_rowptr[node], end = g_rowptr[node + 1];
    for (int e = beg; e < end; e++) {
        int src = g_esrc[e];
        const float4* hp = (const float4*)(g_bufA + (size_t)src * FEAT + lane * 8);
        float4 v0 = hp[0], v1 = hp[1];
        float av = g_asrc[src * H + head] + ad;
        float ee = (av > 0.f) ? av : 0.2f * av;
        float nm = fmaxf(m, ee);
        float scale = __expf(m - nm);
        float w = __expf(ee - nm);
        m = nm;
        s = s * scale + w;
        acc[0] = acc[0] * scale + w * v0.x;
        acc[1] = acc[1] * scale + w * v0.y;
        acc[2] = acc[2] * scale + w * v0.z;
        acc[3] = acc[3] * scale + w * v0.w;
        acc[4] = acc[4] * scale + w * v1.x;
        acc[5] = acc[5] * scale + w * v1.y;
        acc[6] = acc[6] * scale + w * v1.z;
        acc[7] = acc[7] * scale + w * v1.w;
    }
    float inv = (s > 0.f) ? 1.f / s : 0.f;
    const float4* bp = (const float4*)(bias + lane * 8);
    float4 b0 = bp[0], b1 = bp[1];
    float4 o0 = make_float4(fmaxf(acc[0] * inv + b0.x, 0.f), fmaxf(acc[1] * inv + b0.y, 0.f),
                            fmaxf(acc[2] * inv + b0.z, 0.f), fmaxf(acc[3] * inv + b0.w, 0.f));
    float4 o1 = make_float4(fmaxf(acc[4] * inv + b1.x, 0.f), fmaxf(acc[5] * inv + b1.y, 0.f),
                            fmaxf(acc[6] * inv + b1.z, 0.f), fmaxf(acc[7] * inv + b1.w, 0.f));
    float4* op = (float4*)(g_bufB + (size_t)node * FEAT + lane * 8);
    op[0] = o0;
    op[1] = o1;
}

// ---------------- global mean pool (batch is sorted): run-length flush ----
__global__ void k_pool(const int* __restrict__ batch) {
    constexpr int ROWS = 128;
    __shared__ int sb[ROWS];
    int n0 = blockIdx.x * ROWS;
    int tid = threadIdx.x;
    for (int i = tid; i < ROWS; i += 256) {
        int n = n0 + i;
        sb[i] = (n < N_NODES) ? batch[n] : -1;
    }
    __syncthreads();
    float acc = 0.f;
    int cur = sb[0];
    for (int i = 0; i < ROWS; i++) {
        int g = sb[i];
        if (g < 0) break;
        if (g != cur) {
            atomicAdd(&g_pool[cur * FEAT + tid], acc);
            acc = 0.f;
            cur = g;
        }
        acc += g_bufB[(size_t)(n0 + i) * FEAT + tid];
    }
    if (cur >= 0) atomicAdd(&g_pool[cur * FEAT + tid], acc);
}

__global__ void k_cnt(const int* __restrict__ batch) {
    int n = blockIdx.x * blockDim.x + threadIdx.x;
    if (n < N_NODES) atomicAdd(&g_cnt[batch[n]], 1.f);
}

__global__ void k_fc(const float* __restrict__ Wfc, const float* __restrict__ bfc,
                     float* __restrict__ out) {
    int g = blockIdx.x;
    int tid = threadIdx.x;
    __shared__ float p[FEAT];
    float inv = 1.f / fmaxf(g_cnt[g], 1.f);
    p[tid] = g_pool[g * FEAT + tid] * inv;
    __syncthreads();
    float s = bfc[tid];
#pragma unroll 8
    for (int k = 0; k < FEAT; k++) s = fmaf(p[k], Wfc[k * FEAT + tid], s);
    out[g * FEAT + tid] = fmaxf(s, 0.f);
}

// ---------------- launcher -------------------------------------------------
extern "C" void kernel_launch(void* const* d_in, const int* in_sizes, int n_in,
                              void* d_out, int out_size) {
    const float* x        = (const float*)d_in[0];
    const int*   edges    = (const int*)d_in[1];
    const int*   batch    = (const int*)d_in[2];
    const float* W1       = (const float*)d_in[3];
    const float* att_src1 = (const float*)d_in[4];
    const float* att_dst1 = (const float*)d_in[5];
    const float* b1       = (const float*)d_in[6];
    const float* W2       = (const float*)d_in[7];
    const float* att_src2 = (const float*)d_in[8];
    const float* att_dst2 = (const float*)d_in[9];
    const float* b2       = (const float*)d_in[10];
    const float* Wfc      = (const float*)d_in[11];
    const float* bfc      = (const float*)d_in[12];
    float* out = (float*)d_out;

    const int* srcp = edges;
    const int* dstp = edges + N_EDGES;

    static int smem_set = 0;
    if (!smem_set) {
        cudaFuncSetAttribute(k_gemm_wmma, cudaFuncAttributeMaxDynamicSharedMemorySize,
                             SMEM_GEMM);
        smem_set = 1;
    }

    // zero accumulators + build CSR by destination
    k_zero<<<(N_NODES + 256) / 256, 256>>>();
    k_deg<<<(N_EDGES + 255) / 256, 256>>>(dstp);
    k_scan<<<1, 1024>>>();
    k_cursor<<<(N_NODES + 255) / 256, 256>>>();
    k_scatter<<<(N_EDGES + 255) / 256, 256>>>(srcp, dstp);

    dim3 ggrid(M_PAD / 128, FEAT / 128);   // (391, 2)
    int splitA_blocks = (M_PAD * FEAT / 4 + 255) / 256;
    int att_blocks = (N_NODES * 32 + 255) / 256;
    int agg_blocks = (N_NODES + 7) / 8;

    // layer 1 (H=4, C=64)
    k_split_W<<<FEAT, FEAT>>>(W1);
    k_split_A<<<splitA_blocks, 256>>>(x, 0);
    k_gemm_wmma<<<ggrid, 256, SMEM_GEMM>>>();
    k_att<4><<<att_blocks, 256>>>(att_src1, att_dst1);
    k_agg<4><<<agg_blocks, 256>>>(b1);

    // layer 2 (H=1, C=256)
    k_split_W<<<FEAT, FEAT>>>(W2);
    k_split_A<<<splitA_blocks, 256>>>(nullptr, 1);
    k_gemm_wmma<<<ggrid, 256, SMEM_GEMM>>>();
    k_att<1><<<att_blocks, 256>>>(att_src2, att_dst2);
    k_agg<1><<<agg_blocks, 256>>>(b2);

    // pool + FC head
    k_pool<<<(N_NODES + 127) / 128, 256>>>(batch);
    k_cnt<<<(N_NODES + 255) / 256, 256>>>(batch);
    k_fc<<<N_GRAPHS, 256>>>(Wfc, bfc, out);
}

// round 14
// speedup vs baseline: 1.4345x; 1.4307x over previous
#include <cuda_runtime.h>
#include <cuda_bf16.h>
#include <math.h>
#include <stdint.h>

#define N_NODES  50000
#define N_EDGES  800000
#define N_GRAPHS 50
#define FEAT     256
#define M_PAD    50048      // 391 * 128
#define TM_CNT   (M_PAD / 16)   // 3128 m-tiles

// ---------------- scratch (static device globals: no allocations) ----------
__device__ float g_bufA[(size_t)M_PAD * FEAT];     // GEMM output h (padded rows)
__device__ float g_bufB[(size_t)N_NODES * FEAT];   // aggregated/relu output
__device__ float g_asrc[N_NODES * 4];
__device__ float g_adst[N_NODES * 4];
__device__ int   g_rowptr[N_NODES + 1];
__device__ int   g_cursor[N_NODES];
__device__ int   g_esrc[N_EDGES];
__device__ float g_pool[N_GRAPHS * FEAT];
__device__ float g_cnt[N_GRAPHS];
// bf16x3 split operands, stored FRAGMENT-MAJOR for mma.m16n8k16:
//   A tile (16x16) = 128 b32, order [lane][reg0..3]
//   B tile (8n x 16k) = 64 b32, order [lane][reg0..1]
__device__ uint32_t g_Ah[(size_t)TM_CNT * 16 * 128];
__device__ uint32_t g_Al[(size_t)TM_CNT * 16 * 128];
__device__ uint32_t g_Wh[32 * 16 * 64];
__device__ uint32_t g_Wl[32 * 16 * 64];

// ---------------- raw bf16 mma.sync --------------------------------------
#define MMA_BF16(d, a, b)                                                    \
    asm volatile(                                                            \
        "mma.sync.aligned.m16n8k16.row.col.f32.bf16.bf16.f32 "               \
        "{%0,%1,%2,%3}, {%4,%5,%6,%7}, {%8,%9}, {%0,%1,%2,%3};"              \
        : "+f"((d)[0]), "+f"((d)[1]), "+f"((d)[2]), "+f"((d)[3])             \
        : "r"((a).x), "r"((a).y), "r"((a).z), "r"((a).w),                    \
          "r"((b).x), "r"((b).y))

// ================= fragment-major bf16x3 GEMM ==============================
// C[M_PAD,256] = A @ W.  Block tile 128x128; 8 warps of 32(M) x 64(N).
// 3 passes: AhBh + AhBl + AlBh into fp32 acc.  No smem, no syncs.
__global__ __launch_bounds__(256) void k_gemm_mma() {
    int tid = threadIdx.x, w = tid >> 5, lane = tid & 31;
    int warp_m = w >> 1, warp_n = w & 1;
    int tm0 = blockIdx.x * 8 + warp_m * 2;     // first of 2 m-tiles
    int tn0 = blockIdx.y * 16 + warp_n * 8;    // first of 8 n-tiles

    const uint4* Ah4 = (const uint4*)g_Ah;     // tile = 32 uint4
    const uint4* Al4 = (const uint4*)g_Al;
    const uint2* Bh2 = (const uint2*)g_Wh;     // tile = 32 uint2
    const uint2* Bl2 = (const uint2*)g_Wl;

    float acc[2][8][4];
#pragma unroll
    for (int i = 0; i < 2; i++)
#pragma unroll
        for (int j = 0; j < 8; j++)
#pragma unroll
            for (int c = 0; c < 4; c++) acc[i][j][c] = 0.f;

#pragma unroll 2
    for (int tk = 0; tk < 16; tk++) {
        uint4 ah[2], al[2];
#pragma unroll
        for (int i = 0; i < 2; i++) {
            size_t t = ((size_t)(tm0 + i) * 16 + tk) * 32 + lane;
            ah[i] = Ah4[t];
            al[i] = Al4[t];
        }
        uint2 bh[8], bl[8];
#pragma unroll
        for (int j = 0; j < 8; j++) {
            size_t t = ((size_t)(tn0 + j) * 16 + tk) * 32 + lane;
            bh[j] = Bh2[t];
            bl[j] = Bl2[t];
        }
        // pass-major ordering: RAW on same acc is 16 MMAs apart
#pragma unroll
        for (int j = 0; j < 8; j++)
#pragma unroll
            for (int i = 0; i < 2; i++) MMA_BF16(acc[i][j], ah[i], bh[j]);
#pragma unroll
        for (int j = 0; j < 8; j++)
#pragma unroll
            for (int i = 0; i < 2; i++) MMA_BF16(acc[i][j], ah[i], bl[j]);
#pragma unroll
        for (int j = 0; j < 8; j++)
#pragma unroll
            for (int i = 0; i < 2; i++) MMA_BF16(acc[i][j], al[i], bh[j]);
    }

    // epilogue: c0,c1 -> (row, col..col+1); c2,c3 -> (row+8, col..col+1)
    int row_in = lane >> 2, col_in = (lane & 3) * 2;
#pragma unroll
    for (int i = 0; i < 2; i++) {
        int row = tm0 * 16 + i * 16 + row_in;
#pragma unroll
        for (int j = 0; j < 8; j++) {
            int col = (tn0 + j) * 8 + col_in;
            float* cp = g_bufA + (size_t)row * FEAT + col;
            *(float2*)cp = make_float2(acc[i][j][0], acc[i][j][1]);
            *(float2*)(cp + 8 * FEAT) = make_float2(acc[i][j][2], acc[i][j][3]);
        }
    }
}

// ---------------- split A into fragment-major bf16 hi/lo -------------------
// slot s = ((tm*16 + tk)*32 + lane)*4 + reg ; each slot = one b32 (2 k-values)
// row = tm*16 + (lane>>2) + (reg&1)*8 ;  k = tk*16 + (lane&3)*2 + (reg&2)*4
__global__ void k_split_A(const float* __restrict__ ext, int internal) {
    int s = blockIdx.x * blockDim.x + threadIdx.x;
    if (s >= TM_CNT * 16 * 128) return;
    int reg = s & 3, lane = (s >> 2) & 31, tk = (s >> 7) & 15, tm = s >> 11;
    int row = tm * 16 + (lane >> 2) + (reg & 1) * 8;
    int k = tk * 16 + (lane & 3) * 2 + (reg & 2) * 4;
    float2 v = make_float2(0.f, 0.f);
    if (row < N_NODES) {
        const float* src = internal ? g_bufB : ext;
        v = *(const float2*)(src + (size_t)row * FEAT + k);
    }
    __nv_bfloat162 h = __floats2bfloat162_rn(v.x, v.y);
    float2 fh = __bfloat1622float2(h);
    __nv_bfloat162 l = __floats2bfloat162_rn(v.x - fh.x, v.y - fh.y);
    g_Ah[s] = *(uint32_t*)&h;
    g_Al[s] = *(uint32_t*)&l;
}

// ---------------- split W ([k][n] row-major) into fragment-major B ---------
// B tile (tn, tk): lane l, reg r: n = tn*8 + (l>>2), k = tk*16 + (l&3)*2 + r*8
__global__ void k_split_W(const float* __restrict__ W) {
    int s = blockIdx.x * blockDim.x + threadIdx.x;   // 16384 threads
    if (s >= 32 * 16 * 32) return;
    int lane = s & 31, tk = (s >> 5) & 15, tn = s >> 9;
    int n = tn * 8 + (lane >> 2);
    int k0 = tk * 16 + (lane & 3) * 2;
#pragma unroll
    for (int r = 0; r < 2; r++) {
        int k = k0 + r * 8;
        float v0 = W[k * FEAT + n];
        float v1 = W[(k + 1) * FEAT + n];
        __nv_bfloat162 h = __floats2bfloat162_rn(v0, v1);
        float2 fh = __bfloat1622float2(h);
        __nv_bfloat162 l = __floats2bfloat162_rn(v0 - fh.x, v1 - fh.y);
        int o = ((tn * 16 + tk) * 32 + lane) * 2 + r;
        g_Wh[o] = *(uint32_t*)&h;
        g_Wl[o] = *(uint32_t*)&l;
    }
}

// ---------------- zero the per-call accumulators ----------------
__global__ void k_zero() {
    int i = blockIdx.x * blockDim.x + threadIdx.x;
    if (i <= N_NODES) g_rowptr[i] = 0;
    if (i < N_GRAPHS * FEAT) g_pool[i] = 0.f;
    if (i < N_GRAPHS) g_cnt[i] = 0.f;
}

__global__ void k_deg(const int* __restrict__ dst) {
    int e = blockIdx.x * blockDim.x + threadIdx.x;
    if (e < N_EDGES) atomicAdd(&g_rowptr[dst[e] + 1], 1);
}

__global__ void k_scan() {
    const int n = N_NODES + 1;
    const int T = 1024;
    __shared__ int sums[T];
    int t = threadIdx.x;
    const int CH = (n + T - 1) / T;
    int beg = t * CH;
    int end = min(beg + CH, n);
    int s = 0;
    for (int i = beg; i < end; i++) { s += g_rowptr[i]; g_rowptr[i] = s; }
    sums[t] = s;
    __syncthreads();
    for (int off = 1; off < T; off <<= 1) {
        int v = sums[t];
        int u = (t >= off) ? sums[t - off] : 0;
        __syncthreads();
        sums[t] = v + u;
        __syncthreads();
    }
    int add = (t > 0) ? sums[t - 1] : 0;
    if (add)
        for (int i = beg; i < end; i++) g_rowptr[i] += add;
}

__global__ void k_cursor() {
    int i = blockIdx.x * blockDim.x + threadIdx.x;
    if (i < N_NODES) g_cursor[i] = g_rowptr[i];
}

__global__ void k_scatter(const int* __restrict__ src, const int* __restrict__ dst) {
    int e = blockIdx.x * blockDim.x + threadIdx.x;
    if (e < N_EDGES) {
        int pos = atomicAdd(&g_cursor[dst[e]], 1);
        g_esrc[pos] = src[e];
    }
}

// ---------------- per-node attention logits: warp per node ----------------
template <int H>
__global__ void k_att(const float* __restrict__ att_src, const float* __restrict__ att_dst) {
    int node = (blockIdx.x * blockDim.x + threadIdx.x) >> 5;
    if (node >= N_NODES) return;
    int lane = threadIdx.x & 31;
    const float4* hp = (const float4*)(g_bufA + (size_t)node * FEAT + lane * 8);
    float4 h0 = hp[0], h1 = hp[1];
    const float4* sp = (const float4*)(att_src + lane * 8);
    float4 s0 = sp[0], s1 = sp[1];
    const float4* dp = (const float4*)(att_dst + lane * 8);
    float4 d0 = dp[0], d1 = dp[1];
    float ps = h0.x * s0.x + h0.y * s0.y + h0.z * s0.z + h0.w * s0.w +
               h1.x * s1.x + h1.y * s1.y + h1.z * s1.z + h1.w * s1.w;
    float pd = h0.x * d0.x + h0.y * d0.y + h0.z * d0.z + h0.w * d0.w +
               h1.x * d1.x + h1.y * d1.y + h1.z * d1.z + h1.w * d1.w;
    constexpr int G = (FEAT / H) / 8;
#pragma unroll
    for (int off = G >> 1; off > 0; off >>= 1) {
        ps += __shfl_down_sync(0xffffffffu, ps, off, G);
        pd += __shfl_down_sync(0xffffffffu, pd, off, G);
    }
    if ((lane & (G - 1)) == 0) {
        int head = lane / G;
        g_asrc[node * H + head] = ps;
        g_adst[node * H + head] = pd;
    }
}

// ---------------- CSR aggregation with online softmax: warp per dst node --
template <int H>
__global__ void k_agg(const float* __restrict__ bias) {
    int node = (blockIdx.x * blockDim.x + threadIdx.x) >> 5;
    if (node >= N_NODES) return;
    int lane = threadIdx.x & 31;
    constexpr int G = (FEAT / H) / 8;
    int head = lane / G;
    float ad = g_adst[node * H + head];
    float m = -INFINITY, s = 0.f;
    float acc[8] = {0.f, 0.f, 0.f, 0.f, 0.f, 0.f, 0.f, 0.f};
    int beg = g_rowptr[node], end = g_rowptr[node + 1];
    for (int e = beg; e < end; e++) {
        int src = g_esrc[e];
        const float4* hp = (const float4*)(g_bufA + (size_t)src * FEAT + lane * 8);
        float4 v0 = hp[0], v1 = hp[1];
        float av = g_asrc[src * H + head] + ad;
        float ee = (av > 0.f) ? av : 0.2f * av;
        float nm = fmaxf(m, ee);
        float scale = __expf(m - nm);
        float w = __expf(ee - nm);
        m = nm;
        s = s * scale + w;
        acc[0] = acc[0] * scale + w * v0.x;
        acc[1] = acc[1] * scale + w * v0.y;
        acc[2] = acc[2] * scale + w * v0.z;
        acc[3] = acc[3] * scale + w * v0.w;
        acc[4] = acc[4] * scale + w * v1.x;
        acc[5] = acc[5] * scale + w * v1.y;
        acc[6] = acc[6] * scale + w * v1.z;
        acc[7] = acc[7] * scale + w * v1.w;
    }
    float inv = (s > 0.f) ? 1.f / s : 0.f;
    const float4* bp = (const float4*)(bias + lane * 8);
    float4 b0 = bp[0], b1 = bp[1];
    float4 o0 = make_float4(fmaxf(acc[0] * inv + b0.x, 0.f), fmaxf(acc[1] * inv + b0.y, 0.f),
                            fmaxf(acc[2] * inv + b0.z, 0.f), fmaxf(acc[3] * inv + b0.w, 0.f));
    float4 o1 = make_float4(fmaxf(acc[4] * inv + b1.x, 0.f), fmaxf(acc[5] * inv + b1.y, 0.f),
                            fmaxf(acc[6] * inv + b1.z, 0.f), fmaxf(acc[7] * inv + b1.w, 0.f));
    float4* op = (float4*)(g_bufB + (size_t)node * FEAT + lane * 8);
    op[0] = o0;
    op[1] = o1;
}

// ---------------- global mean pool (batch is sorted): run-length flush ----
__global__ void k_pool(const int* __restrict__ batch) {
    constexpr int ROWS = 128;
    __shared__ int sb[ROWS];
    int n0 = blockIdx.x * ROWS;
    int tid = threadIdx.x;
    for (int i = tid; i < ROWS; i += 256) {
        int n = n0 + i;
        sb[i] = (n < N_NODES) ? batch[n] : -1;
    }
    __syncthreads();
    float acc = 0.f;
    int cur = sb[0];
    for (int i = 0; i < ROWS; i++) {
        int g = sb[i];
        if (g < 0) break;
        if (g != cur) {
            atomicAdd(&g_pool[cur * FEAT + tid], acc);
            acc = 0.f;
            cur = g;
        }
        acc += g_bufB[(size_t)(n0 + i) * FEAT + tid];
    }
    if (cur >= 0) atomicAdd(&g_pool[cur * FEAT + tid], acc);
}

__global__ void k_cnt(const int* __restrict__ batch) {
    int n = blockIdx.x * blockDim.x + threadIdx.x;
    if (n < N_NODES) atomicAdd(&g_cnt[batch[n]], 1.f);
}

__global__ void k_fc(const float* __restrict__ Wfc, const float* __restrict__ bfc,
                     float* __restrict__ out) {
    int g = blockIdx.x;
    int tid = threadIdx.x;
    __shared__ float p[FEAT];
    float inv = 1.f / fmaxf(g_cnt[g], 1.f);
    p[tid] = g_pool[g * FEAT + tid] * inv;
    __syncthreads();
    float s = bfc[tid];
#pragma unroll 8
    for (int k = 0; k < FEAT; k++) s = fmaf(p[k], Wfc[k * FEAT + tid], s);
    out[g * FEAT + tid] = fmaxf(s, 0.f);
}

// ---------------- launcher -------------------------------------------------
extern "C" void kernel_launch(void* const* d_in, const int* in_sizes, int n_in,
                              void* d_out, int out_size) {
    const float* x        = (const float*)d_in[0];
    const int*   edges    = (const int*)d_in[1];
    const int*   batch    = (const int*)d_in[2];
    const float* W1       = (const float*)d_in[3];
    const float* att_src1 = (const float*)d_in[4];
    const float* att_dst1 = (const float*)d_in[5];
    const float* b1       = (const float*)d_in[6];
    const float* W2       = (const float*)d_in[7];
    const float* att_src2 = (const float*)d_in[8];
    const float* att_dst2 = (const float*)d_in[9];
    const float* b2       = (const float*)d_in[10];
    const float* Wfc      = (const float*)d_in[11];
    const float* bfc      = (const float*)d_in[12];
    float* out = (float*)d_out;

    const int* srcp = edges;
    const int* dstp = edges + N_EDGES;

    // zero accumulators + build CSR by destination
    k_zero<<<(N_NODES + 256) / 256, 256>>>();
    k_deg<<<(N_EDGES + 255) / 256, 256>>>(dstp);
    k_scan<<<1, 1024>>>();
    k_cursor<<<(N_NODES + 255) / 256, 256>>>();
    k_scatter<<<(N_EDGES + 255) / 256, 256>>>(srcp, dstp);

    dim3 ggrid(M_PAD / 128, 2);                       // (391, 2)
    int splitA_blocks = (TM_CNT * 16 * 128 + 255) / 256;
    int splitW_blocks = (32 * 16 * 32 + 255) / 256;
    int att_blocks = (N_NODES * 32 + 255) / 256;
    int agg_blocks = (N_NODES + 7) / 8;

    // layer 1 (H=4, C=64)
    k_split_W<<<splitW_blocks, 256>>>(W1);
    k_split_A<<<splitA_blocks, 256>>>(x, 0);
    k_gemm_mma<<<ggrid, 256>>>();
    k_att<4><<<att_blocks, 256>>>(att_src1, att_dst1);
    k_agg<4><<<agg_blocks, 256>>>(b1);

    // layer 2 (H=1, C=256)
    k_split_W<<<splitW_blocks, 256>>>(W2);
    k_split_A<<<splitA_blocks, 256>>>(nullptr, 1);
    k_gemm_mma<<<ggrid, 256>>>();
    k_att<1><<<att_blocks, 256>>>(att_src2, att_dst2);
    k_agg<1><<<agg_blocks, 256>>>(b2);

    // pool + FC head
    k_pool<<<(N_NODES + 127) / 128, 256>>>(batch);
    k_cnt<<<(N_NODES + 255) / 256, 256>>>(batch);
    k_fc<<<N_GRAPHS, 256>>>(Wfc, bfc, out);
}

// round 15
// speedup vs baseline: 1.4368x; 1.0015x over previous
#include <cuda_runtime.h>
#include <cuda_bf16.h>
#include <math.h>
#include <stdint.h>

#define N_NODES  50000
#define N_EDGES  800000
#define N_GRAPHS 50
#define FEAT     256
#define M_PAD    50048      // 391 * 128
#define TM_CNT   (M_PAD / 16)   // 3128 m-tiles

// ---------------- scratch (static device globals: no allocations) ----------
__device__ float g_bufA[(size_t)M_PAD * FEAT];     // GEMM output h (padded rows)
__device__ float g_bufB[(size_t)N_NODES * FEAT];   // aggregated/relu output
__device__ float g_asrc[N_NODES * 4];
__device__ float g_adst[N_NODES * 4];
__device__ int   g_rowptr[N_NODES + 1];
__device__ int   g_cursor[N_NODES];
__device__ int   g_esrc[N_EDGES];
__device__ float g_pool[N_GRAPHS * FEAT];
__device__ float g_cnt[N_GRAPHS];
// bf16x3 split operands, stored FRAGMENT-MAJOR for mma.m16n8k16:
//   A tile (16x16) = 128 b32, order [lane][reg0..3]
//   B tile (8n x 16k) = 64 b32, order [lane][reg0..1]
__device__ uint32_t g_Ah[(size_t)TM_CNT * 16 * 128];
__device__ uint32_t g_Al[(size_t)TM_CNT * 16 * 128];
__device__ uint32_t g_Wh[32 * 16 * 64];
__device__ uint32_t g_Wl[32 * 16 * 64];

// ---------------- raw bf16 mma.sync --------------------------------------
#define MMA_BF16(d, a, b)                                                    \
    asm volatile(                                                            \
        "mma.sync.aligned.m16n8k16.row.col.f32.bf16.bf16.f32 "               \
        "{%0,%1,%2,%3}, {%4,%5,%6,%7}, {%8,%9}, {%0,%1,%2,%3};"              \
        : "+f"((d)[0]), "+f"((d)[1]), "+f"((d)[2]), "+f"((d)[3])             \
        : "r"((a).x), "r"((a).y), "r"((a).z), "r"((a).w),                    \
          "r"((b).x), "r"((b).y))

// ================= fragment-major bf16x3 GEMM ==============================
// C[M_PAD,256] = A @ W.  Block tile 128x128; 8 warps of 32(M) x 64(N).
// 3 passes: AhBh + AhBl + AlBh into fp32 acc.  No smem, no syncs.
__global__ __launch_bounds__(256) void k_gemm_mma() {
    int tid = threadIdx.x, w = tid >> 5, lane = tid & 31;
    int warp_m = w >> 1, warp_n = w & 1;
    int tm0 = blockIdx.x * 8 + warp_m * 2;     // first of 2 m-tiles
    int tn0 = blockIdx.y * 16 + warp_n * 8;    // first of 8 n-tiles

    const uint4* Ah4 = (const uint4*)g_Ah;     // tile = 32 uint4
    const uint4* Al4 = (const uint4*)g_Al;
    const uint2* Bh2 = (const uint2*)g_Wh;     // tile = 32 uint2
    const uint2* Bl2 = (const uint2*)g_Wl;

    float acc[2][8][4];
#pragma unroll
    for (int i = 0; i < 2; i++)
#pragma unroll
        for (int j = 0; j < 8; j++)
#pragma unroll
            for (int c = 0; c < 4; c++) acc[i][j][c] = 0.f;

#pragma unroll 2
    for (int tk = 0; tk < 16; tk++) {
        uint4 ah[2], al[2];
#pragma unroll
        for (int i = 0; i < 2; i++) {
            size_t t = ((size_t)(tm0 + i) * 16 + tk) * 32 + lane;
            ah[i] = Ah4[t];
            al[i] = Al4[t];
        }
        uint2 bh[8], bl[8];
#pragma unroll
        for (int j = 0; j < 8; j++) {
            size_t t = ((size_t)(tn0 + j) * 16 + tk) * 32 + lane;
            bh[j] = Bh2[t];
            bl[j] = Bl2[t];
        }
        // pass-major ordering: RAW on same acc is 16 MMAs apart
#pragma unroll
        for (int j = 0; j < 8; j++)
#pragma unroll
            for (int i = 0; i < 2; i++) MMA_BF16(acc[i][j], ah[i], bh[j]);
#pragma unroll
        for (int j = 0; j < 8; j++)
#pragma unroll
            for (int i = 0; i < 2; i++) MMA_BF16(acc[i][j], ah[i], bl[j]);
#pragma unroll
        for (int j = 0; j < 8; j++)
#pragma unroll
            for (int i = 0; i < 2; i++) MMA_BF16(acc[i][j], al[i], bh[j]);
    }

    // epilogue: c0,c1 -> (row, col..col+1); c2,c3 -> (row+8, col..col+1)
    int row_in = lane >> 2, col_in = (lane & 3) * 2;
#pragma unroll
    for (int i = 0; i < 2; i++) {
        int row = tm0 * 16 + i * 16 + row_in;
#pragma unroll
        for (int j = 0; j < 8; j++) {
            int col = (tn0 + j) * 8 + col_in;
            float* cp = g_bufA + (size_t)row * FEAT + col;
            *(float2*)cp = make_float2(acc[i][j][0], acc[i][j][1]);
            *(float2*)(cp + 8 * FEAT) = make_float2(acc[i][j][2], acc[i][j][3]);
        }
    }
}

// ---------------- split A into fragment-major bf16 hi/lo -------------------
// slot s = ((tm*16 + tk)*32 + lane)*4 + reg ; each slot = one b32 (2 k-values)
// row = tm*16 + (lane>>2) + (reg&1)*8 ;  k = tk*16 + (lane&3)*2 + (reg&2)*4
__global__ void k_split_A(const float* __restrict__ ext, int internal) {
    int s = blockIdx.x * blockDim.x + threadIdx.x;
    if (s >= TM_CNT * 16 * 128) return;
    int reg = s & 3, lane = (s >> 2) & 31, tk = (s >> 7) & 15, tm = s >> 11;
    int row = tm * 16 + (lane >> 2) + (reg & 1) * 8;
    int k = tk * 16 + (lane & 3) * 2 + (reg & 2) * 4;
    float2 v = make_float2(0.f, 0.f);
    if (row < N_NODES) {
        const float* src = internal ? g_bufB : ext;
        v = *(const float2*)(src + (size_t)row * FEAT + k);
    }
    __nv_bfloat162 h = __floats2bfloat162_rn(v.x, v.y);
    float2 fh = __bfloat1622float2(h);
    __nv_bfloat162 l = __floats2bfloat162_rn(v.x - fh.x, v.y - fh.y);
    g_Ah[s] = *(uint32_t*)&h;
    g_Al[s] = *(uint32_t*)&l;
}

// ---------------- split W ([k][n] row-major) into fragment-major B ---------
// B tile (tn, tk): lane l, reg r: n = tn*8 + (l>>2), k = tk*16 + (l&3)*2 + r*8
__global__ void k_split_W(const float* __restrict__ W) {
    int s = blockIdx.x * blockDim.x + threadIdx.x;   // 16384 threads
    if (s >= 32 * 16 * 32) return;
    int lane = s & 31, tk = (s >> 5) & 15, tn = s >> 9;
    int n = tn * 8 + (lane >> 2);
    int k0 = tk * 16 + (lane & 3) * 2;
#pragma unroll
    for (int r = 0; r < 2; r++) {
        int k = k0 + r * 8;
        float v0 = W[k * FEAT + n];
        float v1 = W[(k + 1) * FEAT + n];
        __nv_bfloat162 h = __floats2bfloat162_rn(v0, v1);
        float2 fh = __bfloat1622float2(h);
        __nv_bfloat162 l = __floats2bfloat162_rn(v0 - fh.x, v1 - fh.y);
        int o = ((tn * 16 + tk) * 32 + lane) * 2 + r;
        g_Wh[o] = *(uint32_t*)&h;
        g_Wl[o] = *(uint32_t*)&l;
    }
}

// ---------------- zero the per-call accumulators ----------------
__global__ void k_zero() {
    int i = blockIdx.x * blockDim.x + threadIdx.x;
    if (i <= N_NODES) g_rowptr[i] = 0;
    if (i < N_GRAPHS * FEAT) g_pool[i] = 0.f;
    if (i < N_GRAPHS) g_cnt[i] = 0.f;
}

__global__ void k_deg(const int* __restrict__ dst) {
    int e = blockIdx.x * blockDim.x + threadIdx.x;
    if (e < N_EDGES) atomicAdd(&g_rowptr[dst[e] + 1], 1);
}

__global__ void k_scan() {
    const int n = N_NODES + 1;
    const int T = 1024;
    __shared__ int sums[T];
    int t = threadIdx.x;
    const int CH = (n + T - 1) / T;
    int beg = t * CH;
    int end = min(beg + CH, n);
    int s = 0;
    for (int i = beg; i < end; i++) { s += g_rowptr[i]; g_rowptr[i] = s; }
    sums[t] = s;
    __syncthreads();
    for (int off = 1; off < T; off <<= 1) {
        int v = sums[t];
        int u = (t >= off) ? sums[t - off] : 0;
        __syncthreads();
        sums[t] = v + u;
        __syncthreads();
    }
    int add = (t > 0) ? sums[t - 1] : 0;
    if (add)
        for (int i = beg; i < end; i++) g_rowptr[i] += add;
}

__global__ void k_cursor() {
    int i = blockIdx.x * blockDim.x + threadIdx.x;
    if (i < N_NODES) g_cursor[i] = g_rowptr[i];
}

__global__ void k_scatter(const int* __restrict__ src, const int* __restrict__ dst) {
    int e = blockIdx.x * blockDim.x + threadIdx.x;
    if (e < N_EDGES) {
        int pos = atomicAdd(&g_cursor[dst[e]], 1);
        g_esrc[pos] = src[e];
    }
}

// ---------------- per-node attention logits: warp per node ----------------
template <int H>
__global__ void k_att(const float* __restrict__ att_src, const float* __restrict__ att_dst) {
    int node = (blockIdx.x * blockDim.x + threadIdx.x) >> 5;
    if (node >= N_NODES) return;
    int lane = threadIdx.x & 31;
    const float4* hp = (const float4*)(g_bufA + (size_t)node * FEAT + lane * 8);
    float4 h0 = hp[0], h1 = hp[1];
    const float4* sp = (const float4*)(att_src + lane * 8);
    float4 s0 = sp[0], s1 = sp[1];
    const float4* dp = (const float4*)(att_dst + lane * 8);
    float4 d0 = dp[0], d1 = dp[1];
    float ps = h0.x * s0.x + h0.y * s0.y + h0.z * s0.z + h0.w * s0.w +
               h1.x * s1.x + h1.y * s1.y + h1.z * s1.z + h1.w * s1.w;
    float pd = h0.x * d0.x + h0.y * d0.y + h0.z * d0.z + h0.w * d0.w +
               h1.x * d1.x + h1.y * d1.y + h1.z * d1.z + h1.w * d1.w;
    constexpr int G = (FEAT / H) / 8;
#pragma unroll
    for (int off = G >> 1; off > 0; off >>= 1) {
        ps += __shfl_down_sync(0xffffffffu, ps, off, G);
        pd += __shfl_down_sync(0xffffffffu, pd, off, G);
    }
    if ((lane & (G - 1)) == 0) {
        int head = lane / G;
        g_asrc[node * H + head] = ps;
        g_adst[node * H + head] = pd;
    }
}

// ---------------- CSR aggregation with online softmax: warp per dst node --
template <int H>
__global__ void k_agg(const float* __restrict__ bias) {
    int node = (blockIdx.x * blockDim.x + threadIdx.x) >> 5;
    if (node >= N_NODES) return;
    int lane = threadIdx.x & 31;
    constexpr int G = (FEAT / H) / 8;
    int head = lane / G;
    float ad = g_adst[node * H + head];
    float m = -INFINITY, s = 0.f;
    float acc[8] = {0.f, 0.f, 0.f, 0.f, 0.f, 0.f, 0.f, 0.f};
    int beg = g_rowptr[node], end = g_rowptr[node + 1];
    for (int e = beg; e < end; e++) {
        int src = g_esrc[e];
        const float4* hp = (const float4*)(g_bufA + (size_t)src * FEAT + lane * 8);
        float4 v0 = hp[0], v1 = hp[1];
        float av = g_asrc[src * H + head] + ad;
        float ee = (av > 0.f) ? av : 0.2f * av;
        float nm = fmaxf(m, ee);
        float scale = __expf(m - nm);
        float w = __expf(ee - nm);
        m = nm;
        s = s * scale + w;
        acc[0] = acc[0] * scale + w * v0.x;
        acc[1] = acc[1] * scale + w * v0.y;
        acc[2] = acc[2] * scale + w * v0.z;
        acc[3] = acc[3] * scale + w * v0.w;
        acc[4] = acc[4] * scale + w * v1.x;
        acc[5] = acc[5] * scale + w * v1.y;
        acc[6] = acc[6] * scale + w * v1.z;
        acc[7] = acc[7] * scale + w * v1.w;
    }
    float inv = (s > 0.f) ? 1.f / s : 0.f;
    const float4* bp = (const float4*)(bias + lane * 8);
    float4 b0 = bp[0], b1 = bp[1];
    float4 o0 = make_float4(fmaxf(acc[0] * inv + b0.x, 0.f), fmaxf(acc[1] * inv + b0.y, 0.f),
                            fmaxf(acc[2] * inv + b0.z, 0.f), fmaxf(acc[3] * inv + b0.w, 0.f));
    float4 o1 = make_float4(fmaxf(acc[4] * inv + b1.x, 0.f), fmaxf(acc[5] * inv + b1.y, 0.f),
                            fmaxf(acc[6] * inv + b1.z, 0.f), fmaxf(acc[7] * inv + b1.w, 0.f));
    float4* op = (float4*)(g_bufB + (size_t)node * FEAT + lane * 8);
    op[0] = o0;
    op[1] = o1;
}

// ---------------- global mean pool (batch is sorted): run-length flush ----
__global__ void k_pool(const int* __restrict__ batch) {
    constexpr int ROWS = 128;
    __shared__ int sb[ROWS];
    int n0 = blockIdx.x * ROWS;
    int tid = threadIdx.x;
    for (int i = tid; i < ROWS; i += 256) {
        int n = n0 + i;
        sb[i] = (n < N_NODES) ? batch[n] : -1;
    }
    __syncthreads();
    float acc = 0.f;
    int cur = sb[0];
    for (int i = 0; i < ROWS; i++) {
        int g = sb[i];
        if (g < 0) break;
        if (g != cur) {
            atomicAdd(&g_pool[cur * FEAT + tid], acc);
            acc = 0.f;
            cur = g;
        }
        acc += g_bufB[(size_t)(n0 + i) * FEAT + tid];
    }
    if (cur >= 0) atomicAdd(&g_pool[cur * FEAT + tid], acc);
}

__global__ void k_cnt(const int* __restrict__ batch) {
    int n = blockIdx.x * blockDim.x + threadIdx.x;
    if (n < N_NODES) atomicAdd(&g_cnt[batch[n]], 1.f);
}

__global__ void k_fc(const float* __restrict__ Wfc, const float* __restrict__ bfc,
                     float* __restrict__ out) {
    int g = blockIdx.x;
    int tid = threadIdx.x;
    __shared__ float p[FEAT];
    float inv = 1.f / fmaxf(g_cnt[g], 1.f);
    p[tid] = g_pool[g * FEAT + tid] * inv;
    __syncthreads();
    float s = bfc[tid];
#pragma unroll 8
    for (int k = 0; k < FEAT; k++) s = fmaf(p[k], Wfc[k * FEAT + tid], s);
    out[g * FEAT + tid] = fmaxf(s, 0.f);
}

// ---------------- launcher -------------------------------------------------
extern "C" void kernel_launch(void* const* d_in, const int* in_sizes, int n_in,
                              void* d_out, int out_size) {
    const float* x        = (const float*)d_in[0];
    const int*   edges    = (const int*)d_in[1];
    const int*   batch    = (const int*)d_in[2];
    const float* W1       = (const float*)d_in[3];
    const float* att_src1 = (const float*)d_in[4];
    const float* att_dst1 = (const float*)d_in[5];
    const float* b1       = (const float*)d_in[6];
    const float* W2       = (const float*)d_in[7];
    const float* att_src2 = (const float*)d_in[8];
    const float* att_dst2 = (const float*)d_in[9];
    const float* b2       = (const float*)d_in[10];
    const float* Wfc      = (const float*)d_in[11];
    const float* bfc      = (const float*)d_in[12];
    float* out = (float*)d_out;

    const int* srcp = edges;
    const int* dstp = edges + N_EDGES;

    // zero accumulators + build CSR by destination
    k_zero<<<(N_NODES + 256) / 256, 256>>>();
    k_deg<<<(N_EDGES + 255) / 256, 256>>>(dstp);
    k_scan<<<1, 1024>>>();
    k_cursor<<<(N_NODES + 255) / 256, 256>>>();
    k_scatter<<<(N_EDGES + 255) / 256, 256>>>(srcp, dstp);

    dim3 ggrid(M_PAD / 128, 2);                       // (391, 2)
    int splitA_blocks = (TM_CNT * 16 * 128 + 255) / 256;
    int splitW_blocks = (32 * 16 * 32 + 255) / 256;
    int att_blocks = (N_NODES * 32 + 255) / 256;
    int agg_blocks = (N_NODES + 7) / 8;

    // layer 1 (H=4, C=64)
    k_split_W<<<splitW_blocks, 256>>>(W1);
    k_split_A<<<splitA_blocks, 256>>>(x, 0);
    k_gemm_mma<<<ggrid, 256>>>();
    k_att<4><<<att_blocks, 256>>>(att_src1, att_dst1);
    k_agg<4><<<agg_blocks, 256>>>(b1);

    // layer 2 (H=1, C=256)
    k_split_W<<<splitW_blocks, 256>>>(W2);
    k_split_A<<<splitA_blocks, 256>>>(nullptr, 1);
    k_gemm_mma<<<ggrid, 256>>>();
    k_att<1><<<att_blocks, 256>>>(att_src2, att_dst2);
    k_agg<1><<<agg_blocks, 256>>>(b2);

    // pool + FC head
    k_pool<<<(N_NODES + 127) / 128, 256>>>(batch);
    k_cnt<<<(N_NODES + 255) / 256, 256>>>(batch);
    k_fc<<<N_GRAPHS, 256>>>(Wfc, bfc, out);
}